// round 2
// baseline (speedup 1.0000x reference)
#include <cuda_runtime.h>

// Problem constants
#define BB    2
#define NN    40000
#define C_IN  64
#define MM    40000
#define KNB   16
#define HH    8
#define C_MID 16

#define WARPS_PER_BLOCK 8
#define POINTS_TOTAL    (BB * MM)   // 80000

__global__ __launch_bounds__(256, 4)
void pcf_kernel(const float* __restrict__ feats,  // [B,N,64]
                const int*   __restrict__ inds,   // [B,M,16] (int32! jax x64 disabled)
                const float* __restrict__ guid,   // [B,M,16,8]
                const float* __restrict__ wnet,   // [B,M,16,16]
                float*       __restrict__ out)    // [B,M,1024]
{
    __shared__ float w_sh[WARPS_PER_BLOCK][KNB][C_MID];  // 8 KB
    __shared__ float g_sh[WARPS_PER_BLOCK][KNB][HH];     // 4 KB

    const int warp = threadIdx.x >> 5;
    const int lane = threadIdx.x & 31;
    const long long p = (long long)blockIdx.x * WARPS_PER_BLOCK + warp; // global point
    if (p >= POINTS_TOTAL) return;

    // --- stage per-point metadata ---
    // neighbor indices: lanes 0..15 hold idx[k] (int32)
    int myidx = 0;
    if (lane < KNB) myidx = inds[p * KNB + lane];

    // weightnet tile: 256 floats = 64 float4, 2 per lane (coalesced)
    {
        const float4* w4 = (const float4*)(wnet + p * (KNB * C_MID));
        float4* ws4 = (float4*)&w_sh[warp][0][0];
        ws4[lane]      = w4[lane];
        ws4[lane + 32] = w4[lane + 32];
    }
    // guidance tile: 128 floats = 32 float4, 1 per lane (coalesced)
    {
        const float4* g4 = (const float4*)(guid + p * (KNB * HH));
        float4* gs4 = (float4*)&g_sh[warp][0][0];
        gs4[lane] = g4[lane];
    }
    __syncwarp();

    const long long b = p / MM;
    // feature rows as float2: lane l reads channels 2l, 2l+1
    const float2* fbase = (const float2*)feats + b * (long long)NN * (C_IN / 2);

    float acc0[C_MID];
    float acc1[C_MID];
#pragma unroll
    for (int d = 0; d < C_MID; d++) { acc0[d] = 0.f; acc1[d] = 0.f; }

#pragma unroll
    for (int k = 0; k < KNB; k++) {
        const int nidx = __shfl_sync(0xffffffffu, myidx, k);
        const float2 f = fbase[(long long)nidx * (C_IN / 2) + lane]; // coalesced 256B row
        const float  g = g_sh[warp][k][lane >> 2];          // head for c=2l,2l+1
        const float a0 = f.x * g;
        const float a1 = f.y * g;
#pragma unroll
        for (int d = 0; d < C_MID; d++) {
            const float w = w_sh[warp][k][d];               // smem broadcast
            acc0[d] = fmaf(a0, w, acc0[d]);
            acc1[d] = fmaf(a1, w, acc1[d]);
        }
    }

    // Output row: 1024 f32; lane l owns [32l, 32l+32) floats = one full 128B line.
    float4* o4 = (float4*)(out + p * (C_IN * C_MID)) + lane * 8;
#pragma unroll
    for (int i = 0; i < 4; i++)
        o4[i] = make_float4(acc0[4*i], acc0[4*i+1], acc0[4*i+2], acc0[4*i+3]);
#pragma unroll
    for (int i = 0; i < 4; i++)
        o4[4 + i] = make_float4(acc1[4*i], acc1[4*i+1], acc1[4*i+2], acc1[4*i+3]);
}

extern "C" void kernel_launch(void* const* d_in, const int* in_sizes, int n_in,
                              void* d_out, int out_size)
{
    const float* feats = (const float*)d_in[0];
    const int*   inds  = (const int*)d_in[1];
    const float* guid  = (const float*)d_in[2];
    const float* wnet  = (const float*)d_in[3];
    float*       out   = (float*)d_out;

    const int blocks = (POINTS_TOTAL + WARPS_PER_BLOCK - 1) / WARPS_PER_BLOCK; // 10000
    pcf_kernel<<<blocks, 256>>>(feats, inds, guid, wnet, out);
}

// round 3
// speedup vs baseline: 1.5270x; 1.5270x over previous
#include <cuda_runtime.h>

#define BB    2
#define NN    40000
#define C_IN  64
#define MM    40000
#define KNB   16
#define HH    8
#define C_MID 16

#define WARPS_PER_BLOCK 8
#define POINTS_TOTAL    (BB * MM)   // 80000

typedef unsigned long long ull;

__device__ __forceinline__ ull pack2(float lo, float hi) {
    ull r; asm("mov.b64 %0,{%1,%2};" : "=l"(r) : "f"(lo), "f"(hi)); return r;
}
__device__ __forceinline__ void unpack2(float& lo, float& hi, ull v) {
    asm("mov.b64 {%0,%1},%2;" : "=f"(lo), "=f"(hi) : "l"(v));
}
__device__ __forceinline__ ull mul2(ull a, ull b) {
    ull r; asm("mul.rn.f32x2 %0,%1,%2;" : "=l"(r) : "l"(a), "l"(b)); return r;
}
__device__ __forceinline__ void fma2(ull& d, ull a, ull b) {
    asm("fma.rn.f32x2 %0,%1,%2,%3;" : "=l"(d) : "l"(a), "l"(b), "l"(d));
}

// Per-warp smem region: 1152 floats (4.5KB).
//   Phase 1 (staging): [0..255] = w tile [16][16], [256..383] = g tile [16][8]
//   Phase 2 (epilogue): whole region reused as padded transpose buffer
//     (logical float4 L4: owner t=L4>>3, j=L4&7, phys4 = 9*t + j; max 286 < 288)
#define REGION_F 1152

__global__ __launch_bounds__(256, 4)
void pcf_kernel(const float* __restrict__ feats,  // [B,N,64]
                const int*   __restrict__ inds,   // [B,M,16] int32
                const float* __restrict__ guid,   // [B,M,16,8]
                const float* __restrict__ wnet,   // [B,M,16,16]
                float*       __restrict__ out)    // [B,M,1024]
{
    __shared__ float region[WARPS_PER_BLOCK][REGION_F];

    const int warp = threadIdx.x >> 5;
    const int lane = threadIdx.x & 31;
    const long long p = (long long)blockIdx.x * WARPS_PER_BLOCK + warp; // exact grid

    float* w_sh = &region[warp][0];     // [16][16]
    float* g_sh = &region[warp][256];   // [16][8]

    // --- stage per-point tiles (coalesced) ---
    int myidx = 0;
    if (lane < KNB) myidx = inds[p * KNB + lane];
    {
        const float4* w4 = (const float4*)(wnet + p * (KNB * C_MID));
        float4* ws4 = (float4*)w_sh;
        ws4[lane]      = w4[lane];
        ws4[lane + 32] = w4[lane + 32];
        const float4* g4 = (const float4*)(guid + p * (KNB * HH));
        ((float4*)g_sh)[lane] = g4[lane];
    }
    __syncwarp();

    const long long b = p / MM;
    const float2* fbase = (const float2*)feats + b * (long long)NN * (C_IN / 2);

    // acc[d] = packed (c0, c1) accumulator pair, c0 = 2*lane, c1 = 2*lane+1
    ull acc[C_MID];
#pragma unroll
    for (int d = 0; d < C_MID; d++) acc[d] = 0ull;

#pragma unroll
    for (int k = 0; k < KNB; k++) {
        const int nidx = __shfl_sync(0xffffffffu, myidx, k);
        const float2 f = fbase[(long long)nidx * (C_IN / 2) + lane]; // 256B coalesced
        const float  g = g_sh[k * HH + (lane >> 2)];
        const ull a2 = mul2(pack2(f.x, f.y), pack2(g, g));

        const float4 w0 = ((const float4*)(w_sh + k * C_MID))[0];
        const float4 w1 = ((const float4*)(w_sh + k * C_MID))[1];
        const float4 w2 = ((const float4*)(w_sh + k * C_MID))[2];
        const float4 w3 = ((const float4*)(w_sh + k * C_MID))[3];

        fma2(acc[0],  a2, pack2(w0.x, w0.x));
        fma2(acc[1],  a2, pack2(w0.y, w0.y));
        fma2(acc[2],  a2, pack2(w0.z, w0.z));
        fma2(acc[3],  a2, pack2(w0.w, w0.w));
        fma2(acc[4],  a2, pack2(w1.x, w1.x));
        fma2(acc[5],  a2, pack2(w1.y, w1.y));
        fma2(acc[6],  a2, pack2(w1.z, w1.z));
        fma2(acc[7],  a2, pack2(w1.w, w1.w));
        fma2(acc[8],  a2, pack2(w2.x, w2.x));
        fma2(acc[9],  a2, pack2(w2.y, w2.y));
        fma2(acc[10], a2, pack2(w2.z, w2.z));
        fma2(acc[11], a2, pack2(w2.w, w2.w));
        fma2(acc[12], a2, pack2(w3.x, w3.x));
        fma2(acc[13], a2, pack2(w3.y, w3.y));
        fma2(acc[14], a2, pack2(w3.z, w3.z));
        fma2(acc[15], a2, pack2(w3.w, w3.w));
    }

    // --- epilogue: transpose through smem so STG is fully coalesced ---
    // Thread t's 32 output floats = out row floats [32t, 32t+32):
    //   [32t,32t+16)  = c0 row = lo components of acc[0..15]
    //   [32t+16,+16)  = c1 row = hi components of acc[0..15]
    __syncwarp();   // staging tiles dead; reuse region as transpose buffer
    float4* b4 = (float4*)&region[warp][0];

#pragma unroll
    for (int j = 0; j < 4; j++) {
        float l0, h0, l1, h1, l2, h2, l3, h3;
        unpack2(l0, h0, acc[4*j + 0]);
        unpack2(l1, h1, acc[4*j + 1]);
        unpack2(l2, h2, acc[4*j + 2]);
        unpack2(l3, h3, acc[4*j + 3]);
        b4[9 * lane + j]     = make_float4(l0, l1, l2, l3);   // logical f4 8t+j
        b4[9 * lane + 4 + j] = make_float4(h0, h1, h2, h3);   // logical f4 8t+4+j
    }
    __syncwarp();

    float4* og = (float4*)(out + p * (C_IN * C_MID));
#pragma unroll
    for (int i = 0; i < 8; i++) {
        const int L4 = 32 * i + lane;                 // consecutive across warp
        og[L4] = b4[9 * (L4 >> 3) + (L4 & 7)];
    }
}

extern "C" void kernel_launch(void* const* d_in, const int* in_sizes, int n_in,
                              void* d_out, int out_size)
{
    const float* feats = (const float*)d_in[0];
    const int*   inds  = (const int*)d_in[1];
    const float* guid  = (const float*)d_in[2];
    const float* wnet  = (const float*)d_in[3];
    float*       out   = (float*)d_out;

    const int blocks = POINTS_TOTAL / WARPS_PER_BLOCK; // 10000 exact
    pcf_kernel<<<blocks, 256>>>(feats, inds, guid, wnet, out);
}